// round 6
// baseline (speedup 1.0000x reference)
#include <cuda_runtime.h>
#include <cuda_fp16.h>
#include <stdint.h>
#include <math.h>

// ---------------- problem constants ----------------
#define BN_ 8192   // batch
#define DN_ 2048   // feature dim
#define NI_ 1023   // inner nodes
#define NL_ 1024   // leaves / padded inner count
#define CN_ 1000   // classes

// ---------------- device-global scratch ----------------
__device__ __half g_xh[(size_t)BN_ * DN_];        // x in fp16
__device__ __half g_WhT[NL_ * DN_];               // W^T padded fp16: [1024 n][2048 k]
__device__ float  g_bp[NL_];
__device__ float  g_dec[(size_t)BN_ * NL_];       // decisions [8192][1024] (fp32)
__device__ __half g_pph[(size_t)BN_ * NL_];       // path probs fp16 [8192][1024]
__device__ __half g_lph[NL_ * NL_];               // softmax(leaf) fp16 [1024 leaf][1024 cls pad]

// ---------------- helpers ----------------
__device__ __forceinline__ uint32_t smem_u32(const void* p) {
    uint32_t a;
    asm("{ .reg .u64 t; cvta.to.shared.u64 t, %1; cvt.u32.u64 %0, t; }" : "=r"(a) : "l"(p));
    return a;
}
__device__ __forceinline__ void cpasync16(uint32_t dst, const void* src) {
    asm volatile("cp.async.cg.shared.global [%0], [%1], 16;" :: "r"(dst), "l"(src) : "memory");
}
__device__ __forceinline__ void ldsm4(uint32_t* r, uint32_t addr) {
    asm volatile("ldmatrix.sync.aligned.m8n8.x4.shared.b16 {%0,%1,%2,%3}, [%4];"
        : "=r"(r[0]), "=r"(r[1]), "=r"(r[2]), "=r"(r[3]) : "r"(addr));
}
__device__ __forceinline__ void ldsm4t(uint32_t* r, uint32_t addr) {
    asm volatile("ldmatrix.sync.aligned.m8n8.x4.trans.shared.b16 {%0,%1,%2,%3}, [%4];"
        : "=r"(r[0]), "=r"(r[1]), "=r"(r[2]), "=r"(r[3]) : "r"(addr));
}
__device__ __forceinline__ void mma16816(float* d, const uint32_t* a, uint32_t b0, uint32_t b1) {
    asm volatile("mma.sync.aligned.m16n8k16.row.col.f32.f16.f16.f32 "
        "{%0,%1,%2,%3}, {%4,%5,%6,%7}, {%8,%9}, {%0,%1,%2,%3};"
        : "+f"(d[0]), "+f"(d[1]), "+f"(d[2]), "+f"(d[3])
        : "r"(a[0]), "r"(a[1]), "r"(a[2]), "r"(a[3]), "r"(b0), "r"(b1));
}

// ---------------- prep kernels ----------------
// x fp32 -> fp16 (8 elems per thread)
__global__ __launch_bounds__(256) void convert_x(const float* __restrict__ x) {
    size_t i = ((size_t)blockIdx.x * 256 + threadIdx.x) * 8;
    float4 v0 = *(const float4*)(x + i);
    float4 v1 = *(const float4*)(x + i + 4);
    __half2 h[4];
    h[0] = __floats2half2_rn(v0.x, v0.y);
    h[1] = __floats2half2_rn(v0.z, v0.w);
    h[2] = __floats2half2_rn(v1.x, v1.y);
    h[3] = __floats2half2_rn(v1.z, v1.w);
    *(uint4*)(g_xh + i) = *(uint4*)h;
}

__global__ void pad_b_kernel(const float* __restrict__ b) {
    int i = blockIdx.x * 256 + threadIdx.x;
    if (i < NL_) g_bp[i] = (i < NI_) ? b[i] : 0.0f;
}

// W [2048 k][1023 n] -> g_WhT [1024 n][2048 k] fp16, pad n=1023 with 0
__global__ __launch_bounds__(256) void transpose_W(const float* __restrict__ W) {
    __shared__ float t[32][33];
    int k0 = blockIdx.x * 32, n0 = blockIdx.y * 32;
    int tx = threadIdx.x, ty = threadIdx.y;   // 32 x 8
    #pragma unroll
    for (int i = 0; i < 32; i += 8) {
        int n = n0 + tx;
        t[ty + i][tx] = (n < NI_) ? W[(size_t)(k0 + ty + i) * NI_ + n] : 0.0f;
    }
    __syncthreads();
    #pragma unroll
    for (int i = 0; i < 32; i += 8)
        g_WhT[(size_t)(n0 + ty + i) * DN_ + k0 + tx] = __float2half_rn(t[tx][ty + i]);
}

// softmax rows of leaf_dist [1024, 1000] -> g_lph fp16 [1024, 1024] (pad zeroed), single expf pass
__global__ __launch_bounds__(256) void softmax_kernel(const float* __restrict__ ld) {
    int row = blockIdx.x;
    const float* r = ld + (size_t)row * CN_;
    __half*      o = g_lph + (size_t)row * NL_;
    __shared__ float ex[CN_];
    __shared__ float sred[8];
    int tid = threadIdx.x;

    float mx = -3.4e38f;
    for (int i = tid; i < CN_; i += 256) mx = fmaxf(mx, r[i]);
    #pragma unroll
    for (int s = 16; s; s >>= 1) mx = fmaxf(mx, __shfl_xor_sync(0xffffffffu, mx, s));
    if ((tid & 31) == 0) sred[tid >> 5] = mx;
    __syncthreads();
    mx = sred[0];
    #pragma unroll
    for (int w = 1; w < 8; w++) mx = fmaxf(mx, sred[w]);
    __syncthreads();

    float sum = 0.0f;
    for (int i = tid; i < CN_; i += 256) {
        float e = expf(r[i] - mx);
        ex[i] = e;
        sum += e;
    }
    #pragma unroll
    for (int s = 16; s; s >>= 1) sum += __shfl_xor_sync(0xffffffffu, sum, s);
    if ((tid & 31) == 0) sred[tid >> 5] = sum;
    __syncthreads();
    sum = 0.0f;
    #pragma unroll
    for (int w = 0; w < 8; w++) sum += sred[w];
    float inv = 1.0f / sum;

    for (int i = tid; i < CN_; i += 256) o[i] = __float2half_rn(ex[i] * inv);
    for (int i = CN_ + tid; i < NL_; i += 256) o[i] = __float2half_rn(0.0f);
}

// ---------------- tree path products: sync-free per-leaf unwind (index math verified) ----------------
__global__ __launch_bounds__(256) void pp_kernel() {
    int row = blockIdx.x;
    __shared__ float ds[NL_];
    int tid = threadIdx.x;
    const float* dr = g_dec + (size_t)row * NL_;
    for (int i = tid; i < NL_; i += 256) ds[i] = dr[i];
    __syncthreads();

    __half* po = g_pph + (size_t)row * NL_;
    #pragma unroll
    for (int jj = 0; jj < 4; jj++) {
        int j = tid + jj * 256;
        float p = 1.0f;
        int idx = j;
        #pragma unroll
        for (int d = 9; d >= 0; d--) {
            int L = 1 << d;
            int i2 = (idx < L) ? (idx << 1) : (((idx - L) << 1) | 1);
            bool left = i2 < L;
            int node = (L - 1) + (left ? i2 : (i2 - L));
            float dd = ds[node];
            p *= left ? dd : (1.0f - dd);
            idx = i2 & (L - 1);
        }
        po[j] = __float2half_rn(p);
    }
}

// ---------------- fp16 mma.sync GEMM: 128x128x64, 3-stage cp.async, ldmatrix ----------------
// BTRANS=false: B stored [n][k] K-major (ldb = row length in k)
// BTRANS=true : B stored [k][n] row-major (ldb = row length in n); loaded via ldmatrix.trans
#define BM   128
#define BNT  128
#define BKH  64                                   // k-tile in halves
#define STG  3
#define PADH 72                                   // halves per A/Bn row (144B)
#define PADBT 136                                 // halves per B-trans row (272B)

template <bool SIG, bool BTRANS>
__global__ __launch_bounds__(128, 2) void gemm_h(
    const __half* __restrict__ A, const __half* __restrict__ Bm,
    const float* __restrict__ bias, float* __restrict__ C,
    int K, int lda, int ldb, int ldc, int nvalid)
{
    constexpr int BROWS = BTRANS ? BKH : BNT;
    constexpr int BSTR  = BTRANS ? PADBT : PADH;        // halves
    constexpr int SST_H = BM * PADH + BROWS * BSTR;     // halves per stage

    extern __shared__ __half smh[];
    const int tid  = threadIdx.x;
    const int wid  = tid >> 5, lane = tid & 31;
    const int gid  = lane >> 2, tig = lane & 3;
    const int m0   = (wid & 1) * 64, n0 = (wid >> 1) * 64;
    const int rowBase = blockIdx.y * BM;
    const int colBase = blockIdx.x * BNT;
    const uint32_t sb = smem_u32(smh);

    const __half* Ag = A + (size_t)rowBase * lda;
    const __half* Bg = BTRANS ? (Bm + colBase) : (Bm + (size_t)colBase * ldb);

    // ldmatrix lane addressing
    const int lrow  = (lane & 7) + ((lane >> 3) & 1) * 8;
    const int khalf = (lane >> 4) * 8;
    uint32_t offA[4], offB[4];
    #pragma unroll
    for (int mf = 0; mf < 4; mf++)
        offA[mf] = (uint32_t)(((m0 + mf * 16 + lrow) * PADH + khalf) * 2);
    if (!BTRANS) {
        #pragma unroll
        for (int p = 0; p < 4; p++)
            offB[p] = (uint32_t)((BM * PADH + (n0 + p * 16 + lrow) * PADH + khalf) * 2);
    } else {
        // lanes 0-7: k rows 0-7 @ ncol p*16; 8-15: k rows 8-15; 16-23: k0-7 @ +8; 24-31: k8-15 @ +8
        const int krow = (lane & 7) + ((lane >> 3) & 1) * 8;
        const int ncol = (lane >> 4) * 8;
        #pragma unroll
        for (int p = 0; p < 4; p++)
            offB[p] = (uint32_t)((BM * PADH + krow * PADBT + (n0 + p * 16 + ncol)) * 2);
    }

    float acc[4][8][4];
    #pragma unroll
    for (int mf = 0; mf < 4; mf++)
        #pragma unroll
        for (int nf = 0; nf < 8; nf++)
            #pragma unroll
            for (int q = 0; q < 4; q++) acc[mf][nf][q] = 0.0f;

    const int nkt = K / BKH;

    auto load_stage = [&](int s, int kt) {
        uint32_t abase = sb + (uint32_t)(s * SST_H) * 2;
        uint32_t bbase = abase + BM * PADH * 2;
        const __half* Ak = Ag + kt * BKH;
        #pragma unroll
        for (int i = 0; i < 8; i++) {
            int idx = tid + i * 128;
            int row = idx >> 3, ch = idx & 7;
            cpasync16(abase + (uint32_t)(row * PADH * 2 + ch * 16), Ak + (size_t)row * lda + ch * 8);
        }
        if (!BTRANS) {
            const __half* Bk = Bg + kt * BKH;
            #pragma unroll
            for (int i = 0; i < 8; i++) {
                int idx = tid + i * 128;
                int row = idx >> 3, ch = idx & 7;
                cpasync16(bbase + (uint32_t)(row * PADH * 2 + ch * 16), Bk + (size_t)row * ldb + ch * 8);
            }
        } else {
            const __half* Bk = Bg + (size_t)(kt * BKH) * ldb;
            // 64 rows x 256B = 1024 chunks, 8 per thread
            #pragma unroll
            for (int i = 0; i < 8; i++) {
                int idx = tid + i * 128;
                int row = idx >> 4, ch = idx & 15;
                cpasync16(bbase + (uint32_t)(row * PADBT * 2 + ch * 16), Bk + (size_t)row * ldb + ch * 8);
            }
        }
    };

    load_stage(0, 0);
    asm volatile("cp.async.commit_group;" ::: "memory");
    load_stage(1, 1);
    asm volatile("cp.async.commit_group;" ::: "memory");

    int stage = 0;
    for (int kt = 0; kt < nkt; kt++) {
        asm volatile("cp.async.wait_group 1;" ::: "memory");
        __syncthreads();

        if (kt + 2 < nkt) {
            int s2 = stage + 2; if (s2 >= STG) s2 -= STG;
            load_stage(s2, kt + 2);
        }
        asm volatile("cp.async.commit_group;" ::: "memory");

        uint32_t sbase = sb + (uint32_t)(stage * SST_H) * 2;
        #pragma unroll
        for (int ks = 0; ks < 4; ks++) {
            uint32_t a[4][4], b[4][4];
            #pragma unroll
            for (int mf = 0; mf < 4; mf++) ldsm4(a[mf], sbase + offA[mf] + ks * 32);
            if (!BTRANS) {
                #pragma unroll
                for (int p = 0; p < 4; p++) ldsm4(b[p], sbase + offB[p] + ks * 32);
                // b[p]: r0=(nlo,klo) r1=(nhi,klo) r2=(nlo,khi) r3=(nhi,khi)
                #pragma unroll
                for (int mf = 0; mf < 4; mf++)
                    #pragma unroll
                    for (int p = 0; p < 4; p++) {
                        mma16816(acc[mf][2 * p],     a[mf], b[p][0], b[p][2]);
                        mma16816(acc[mf][2 * p + 1], a[mf], b[p][1], b[p][3]);
                    }
            } else {
                #pragma unroll
                for (int p = 0; p < 4; p++) ldsm4t(b[p], sbase + offB[p] + ks * 16 * PADBT * 2);
                // b[p]: r0=(klo,nlo) r1=(khi,nlo) r2=(klo,nhi) r3=(khi,nhi)
                #pragma unroll
                for (int mf = 0; mf < 4; mf++)
                    #pragma unroll
                    for (int p = 0; p < 4; p++) {
                        mma16816(acc[mf][2 * p],     a[mf], b[p][0], b[p][1]);
                        mma16816(acc[mf][2 * p + 1], a[mf], b[p][2], b[p][3]);
                    }
            }
        }
        stage++; if (stage == STG) stage = 0;
    }

    // epilogue
    #pragma unroll
    for (int mf = 0; mf < 4; mf++) {
        int r0 = rowBase + m0 + mf * 16 + gid;
        #pragma unroll
        for (int nf = 0; nf < 8; nf++) {
            int col = colBase + n0 + nf * 8 + tig * 2;
            float2 v0 = make_float2(acc[mf][nf][0], acc[mf][nf][1]);
            float2 v1 = make_float2(acc[mf][nf][2], acc[mf][nf][3]);
            if (SIG) {
                float b0 = bias[col], b1 = bias[col + 1];
                v0.x = 1.0f / (1.0f + expf(-(v0.x + b0)));
                v0.y = 1.0f / (1.0f + expf(-(v0.y + b1)));
                v1.x = 1.0f / (1.0f + expf(-(v1.x + b0)));
                v1.y = 1.0f / (1.0f + expf(-(v1.y + b1)));
            }
            if (col < nvalid) {
                *(float2*)(C + (size_t)r0 * ldc + col) = v0;
                *(float2*)(C + (size_t)(r0 + 8) * ldc + col) = v1;
            }
        }
    }
}

#define SMEM_G1 (STG * (BM * PADH + BNT * PADH) * 2)    // 110592
#define SMEM_G2 (STG * (BM * PADH + BKH * PADBT) * 2)   // 107520

// ---------------- host launch ----------------
extern "C" void kernel_launch(void* const* d_in, const int* in_sizes, int n_in,
                              void* d_out, int out_size)
{
    const float* x    = (const float*)d_in[0];   // [8192, 2048]
    const float* W    = (const float*)d_in[1];   // [2048, 1023]
    const float* b    = (const float*)d_in[2];   // [1023]
    const float* leaf = (const float*)d_in[3];   // [1024, 1000]
    float*       out  = (float*)d_out;           // [8192, 1000]

    __half *xh, *WhT, *pph, *lph;
    float *bp, *dec;
    cudaGetSymbolAddress((void**)&xh,  g_xh);
    cudaGetSymbolAddress((void**)&WhT, g_WhT);
    cudaGetSymbolAddress((void**)&bp,  g_bp);
    cudaGetSymbolAddress((void**)&dec, g_dec);
    cudaGetSymbolAddress((void**)&pph, g_pph);
    cudaGetSymbolAddress((void**)&lph, g_lph);

    static bool attr_set = false;
    if (!attr_set) {
        cudaFuncSetAttribute(gemm_h<true, false>, cudaFuncAttributeMaxDynamicSharedMemorySize, SMEM_G1);
        cudaFuncSetAttribute(gemm_h<false, true>, cudaFuncAttributeMaxDynamicSharedMemorySize, SMEM_G2);
        attr_set = true;
    }

    // prep
    convert_x<<<(BN_ * DN_) / (256 * 8), 256>>>(x);
    transpose_W<<<dim3(DN_ / 32, NL_ / 32), dim3(32, 8)>>>(W);
    pad_b_kernel<<<4, 256>>>(b);
    softmax_kernel<<<NL_, 256>>>(leaf);

    // 1) decisions = sigmoid(x @ W + b)   [8192,1024] fp32
    gemm_h<true, false><<<dim3(NL_ / BNT, BN_ / BM), 128, SMEM_G1>>>(
        xh, WhT, bp, dec, DN_, DN_, DN_, NL_, NL_);

    // 2) tree expansion -> pp fp16 [8192,1024]
    pp_kernel<<<BN_, 256>>>();

    // 3) out = pp @ softmax(leaf)   [8192,1000]  (B row-major [leaf][cls] via ldmatrix.trans)
    gemm_h<false, true><<<dim3(NL_ / BNT, BN_ / BM), 128, SMEM_G2>>>(
        pph, lph, nullptr, out, NL_, NL_, NL_, CN_, CN_);
}

// round 7
// speedup vs baseline: 1.4347x; 1.4347x over previous
#include <cuda_runtime.h>
#include <cuda_fp16.h>
#include <stdint.h>
#include <math.h>

// ---------------- problem constants ----------------
#define BN_ 8192   // batch
#define DN_ 2048   // feature dim
#define NI_ 1023   // inner nodes
#define NL_ 1024   // leaves / padded inner count
#define CN_ 1000   // classes

// ---------------- device-global scratch ----------------
__device__ __half g_xh[(size_t)BN_ * DN_];        // x in fp16
__device__ __half g_WhT[NL_ * DN_];               // W^T padded fp16: [1024 n][2048 k]
__device__ float  g_bp[NL_];
__device__ float  g_dec[(size_t)BN_ * NL_];       // decisions [8192][1024] (fp32)
__device__ __half g_pph[(size_t)BN_ * NL_];       // path probs fp16 [8192][1024]
__device__ float  g_lp[NL_ * NL_];                // softmax(leaf) fp32 [1024][1024]
__device__ __half g_lpTh[NL_ * NL_];              // transposed fp16 [1024 cls][1024 leaf]

// ---------------- helpers ----------------
__device__ __forceinline__ uint32_t smem_u32(const void* p) {
    uint32_t a;
    asm("{ .reg .u64 t; cvta.to.shared.u64 t, %1; cvt.u32.u64 %0, t; }" : "=r"(a) : "l"(p));
    return a;
}
__device__ __forceinline__ void cpasync16(uint32_t dst, const void* src) {
    asm volatile("cp.async.cg.shared.global [%0], [%1], 16;" :: "r"(dst), "l"(src) : "memory");
}
__device__ __forceinline__ void ldsm4(uint32_t* r, uint32_t addr) {
    asm volatile("ldmatrix.sync.aligned.m8n8.x4.shared.b16 {%0,%1,%2,%3}, [%4];"
        : "=r"(r[0]), "=r"(r[1]), "=r"(r[2]), "=r"(r[3]) : "r"(addr));
}
__device__ __forceinline__ void mma16816(float* d, const uint32_t* a, uint32_t b0, uint32_t b1) {
    asm volatile("mma.sync.aligned.m16n8k16.row.col.f32.f16.f16.f32 "
        "{%0,%1,%2,%3}, {%4,%5,%6,%7}, {%8,%9}, {%0,%1,%2,%3};"
        : "+f"(d[0]), "+f"(d[1]), "+f"(d[2]), "+f"(d[3])
        : "r"(a[0]), "r"(a[1]), "r"(a[2]), "r"(a[3]), "r"(b0), "r"(b1));
}

// ---------------- prep kernels ----------------
// x fp32 -> fp16 (8 elems per thread)
__global__ __launch_bounds__(256) void convert_x(const float* __restrict__ x) {
    size_t i = ((size_t)blockIdx.x * 256 + threadIdx.x) * 8;
    float4 v0 = *(const float4*)(x + i);
    float4 v1 = *(const float4*)(x + i + 4);
    __half2 h[4];
    h[0] = __floats2half2_rn(v0.x, v0.y);
    h[1] = __floats2half2_rn(v0.z, v0.w);
    h[2] = __floats2half2_rn(v1.x, v1.y);
    h[3] = __floats2half2_rn(v1.z, v1.w);
    *(uint4*)(g_xh + i) = *(uint4*)h;
}

__global__ void pad_b_kernel(const float* __restrict__ b) {
    int i = blockIdx.x * 256 + threadIdx.x;
    if (i < NL_) g_bp[i] = (i < NI_) ? b[i] : 0.0f;
}

// W [2048 k][1023 n] -> g_WhT [1024 n][2048 k] fp16, pad n=1023 with 0
__global__ __launch_bounds__(256) void transpose_W(const float* __restrict__ W) {
    __shared__ float t[32][33];
    int k0 = blockIdx.x * 32, n0 = blockIdx.y * 32;
    int tx = threadIdx.x, ty = threadIdx.y;   // 32 x 8
    #pragma unroll
    for (int i = 0; i < 32; i += 8) {
        int n = n0 + tx;
        t[ty + i][tx] = (n < NI_) ? W[(size_t)(k0 + ty + i) * NI_ + n] : 0.0f;
    }
    __syncthreads();
    #pragma unroll
    for (int i = 0; i < 32; i += 8)
        g_WhT[(size_t)(n0 + ty + i) * DN_ + k0 + tx] = __float2half_rn(t[tx][ty + i]);
}

// softmax rows of leaf_dist [1024, 1000] -> g_lp [1024, 1024] fp32 (pad zeroed)
__global__ __launch_bounds__(256) void softmax_kernel(const float* __restrict__ ld) {
    int row = blockIdx.x;
    const float* r = ld + (size_t)row * CN_;
    float*       o = g_lp + (size_t)row * NL_;
    __shared__ float sred[8];
    int tid = threadIdx.x;

    float mx = -3.4e38f;
    for (int i = tid; i < CN_; i += 256) mx = fmaxf(mx, r[i]);
    #pragma unroll
    for (int s = 16; s; s >>= 1) mx = fmaxf(mx, __shfl_xor_sync(0xffffffffu, mx, s));
    if ((tid & 31) == 0) sred[tid >> 5] = mx;
    __syncthreads();
    mx = sred[0];
    #pragma unroll
    for (int w = 1; w < 8; w++) mx = fmaxf(mx, sred[w]);
    __syncthreads();

    float sum = 0.0f;
    for (int i = tid; i < CN_; i += 256) sum += expf(r[i] - mx);
    #pragma unroll
    for (int s = 16; s; s >>= 1) sum += __shfl_xor_sync(0xffffffffu, sum, s);
    if ((tid & 31) == 0) sred[tid >> 5] = sum;
    __syncthreads();
    sum = 0.0f;
    #pragma unroll
    for (int w = 0; w < 8; w++) sum += sred[w];
    float inv = 1.0f / sum;

    for (int i = tid; i < CN_; i += 256) o[i] = expf(r[i] - mx) * inv;
    for (int i = CN_ + tid; i < NL_; i += 256) o[i] = 0.0f;
}

// g_lp [leaf][cls] fp32 -> g_lpTh [cls][leaf] fp16
__global__ __launch_bounds__(256) void transpose_lp() {
    __shared__ float t[32][33];
    int r0 = blockIdx.x * 32, c0 = blockIdx.y * 32;
    int tx = threadIdx.x, ty = threadIdx.y;
    #pragma unroll
    for (int i = 0; i < 32; i += 8)
        t[ty + i][tx] = g_lp[(size_t)(r0 + ty + i) * NL_ + c0 + tx];
    __syncthreads();
    #pragma unroll
    for (int i = 0; i < 32; i += 8)
        g_lpTh[(size_t)(c0 + ty + i) * NL_ + r0 + tx] = __float2half_rn(t[tx][ty + i]);
}

// ---------------- tree path products: sync-free per-leaf unwind (verified in R6 run) ----------------
__global__ __launch_bounds__(256) void pp_kernel() {
    int row = blockIdx.x;
    __shared__ float ds[NL_];
    int tid = threadIdx.x;
    const float* dr = g_dec + (size_t)row * NL_;
    for (int i = tid; i < NL_; i += 256) ds[i] = dr[i];
    __syncthreads();

    __half* po = g_pph + (size_t)row * NL_;
    #pragma unroll
    for (int jj = 0; jj < 4; jj++) {
        int j = tid + jj * 256;
        float p = 1.0f;
        int idx = j;
        #pragma unroll
        for (int d = 9; d >= 0; d--) {
            int L = 1 << d;
            int i2 = (idx < L) ? (idx << 1) : (((idx - L) << 1) | 1);
            bool left = i2 < L;
            int node = (L - 1) + (left ? i2 : (i2 - L));
            float dd = ds[node];
            p *= left ? dd : (1.0f - dd);
            idx = i2 & (L - 1);
        }
        po[j] = __float2half_rn(p);
    }
}

// ---------------- fp16 mma.sync GEMM: 128x128x64, 3-stage cp.async, ldmatrix (R5-verified) ----------------
#define BM   128
#define BNT  128
#define BKH  64                                   // k-tile in halves
#define STG  3
#define PADH 72                                   // halves per smem row (144B: 16B-aligned, ldsm conflict-free)
#define SSTAGE_H ((BM + BNT) * PADH)              // halves per stage = 18432
#define SMEM_GEMM (STG * SSTAGE_H * 2)            // 110592 bytes

template <bool SIG>
__global__ __launch_bounds__(128, 2) void gemm_h(
    const __half* __restrict__ A, const __half* __restrict__ Bm,
    const float* __restrict__ bias, float* __restrict__ C,
    int K, int lda, int ldb, int ldc, int nvalid)
{
    extern __shared__ __half smh[];
    const int tid  = threadIdx.x;
    const int wid  = tid >> 5, lane = tid & 31;
    const int gid  = lane >> 2, tig = lane & 3;
    const int m0   = (wid & 1) * 64, n0 = (wid >> 1) * 64;
    const int rowBase = blockIdx.y * BM;
    const int colBase = blockIdx.x * BNT;
    const uint32_t sb = smem_u32(smh);

    const __half* Ag = A + (size_t)rowBase * lda;
    const __half* Bg = Bm + (size_t)colBase * ldb;

    // ldmatrix lane addressing: tiles (rows0-7,klo),(rows8-15,klo),(rows0-7,khi),(rows8-15,khi)
    const int lrow  = (lane & 7) + ((lane >> 3) & 1) * 8;
    const int khalf = (lane >> 4) * 8;
    uint32_t offA[4], offB[4];
    #pragma unroll
    for (int mf = 0; mf < 4; mf++)
        offA[mf] = (uint32_t)(((m0 + mf * 16 + lrow) * PADH + khalf) * 2);
    #pragma unroll
    for (int p = 0; p < 4; p++)
        offB[p] = (uint32_t)((BM * PADH + (n0 + p * 16 + lrow) * PADH + khalf) * 2);

    float acc[4][8][4];
    #pragma unroll
    for (int mf = 0; mf < 4; mf++)
        #pragma unroll
        for (int nf = 0; nf < 8; nf++)
            #pragma unroll
            for (int q = 0; q < 4; q++) acc[mf][nf][q] = 0.0f;

    const int nkt = K / BKH;

    // stage loader: 256 rows x 128B, 8x16B chunks per row; 16 chunks per thread
    auto load_stage = [&](int s, int kt) {
        uint32_t abase = sb + (uint32_t)(s * SSTAGE_H) * 2;
        uint32_t bbase = abase + BM * PADH * 2;
        const __half* Ak = Ag + kt * BKH;
        const __half* Bk = Bg + kt * BKH;
        #pragma unroll
        for (int i = 0; i < 8; i++) {
            int idx = tid + i * 128;
            int row = idx >> 3, ch = idx & 7;
            cpasync16(abase + (uint32_t)(row * PADH * 2 + ch * 16), Ak + (size_t)row * lda + ch * 8);
        }
        #pragma unroll
        for (int i = 0; i < 8; i++) {
            int idx = tid + i * 128;
            int row = idx >> 3, ch = idx & 7;
            cpasync16(bbase + (uint32_t)(row * PADH * 2 + ch * 16), Bk + (size_t)row * ldb + ch * 8);
        }
    };

    load_stage(0, 0);
    asm volatile("cp.async.commit_group;" ::: "memory");
    load_stage(1, 1);
    asm volatile("cp.async.commit_group;" ::: "memory");

    int stage = 0;
    for (int kt = 0; kt < nkt; kt++) {
        asm volatile("cp.async.wait_group 1;" ::: "memory");
        __syncthreads();

        if (kt + 2 < nkt) {
            int s2 = stage + 2; if (s2 >= STG) s2 -= STG;
            load_stage(s2, kt + 2);
        }
        asm volatile("cp.async.commit_group;" ::: "memory");

        uint32_t sbase = sb + (uint32_t)(stage * SSTAGE_H) * 2;
        #pragma unroll
        for (int ks = 0; ks < 4; ks++) {
            const uint32_t kb = ks * 32;   // 16 halves per kstep
            uint32_t a[4][4], b[4][4];
            #pragma unroll
            for (int mf = 0; mf < 4; mf++) ldsm4(a[mf], sbase + offA[mf] + kb);
            #pragma unroll
            for (int p = 0; p < 4; p++)   ldsm4(b[p],  sbase + offB[p] + kb);
            // b[p]: r0=(nlo,klo) r1=(nhi,klo) r2=(nlo,khi) r3=(nhi,khi)
            #pragma unroll
            for (int mf = 0; mf < 4; mf++)
                #pragma unroll
                for (int p = 0; p < 4; p++) {
                    mma16816(acc[mf][2 * p],     a[mf], b[p][0], b[p][2]);
                    mma16816(acc[mf][2 * p + 1], a[mf], b[p][1], b[p][3]);
                }
        }
        stage++; if (stage == STG) stage = 0;
    }

    // epilogue
    #pragma unroll
    for (int mf = 0; mf < 4; mf++) {
        int r0 = rowBase + m0 + mf * 16 + gid;
        #pragma unroll
        for (int nf = 0; nf < 8; nf++) {
            int col = colBase + n0 + nf * 8 + tig * 2;
            float2 v0 = make_float2(acc[mf][nf][0], acc[mf][nf][1]);
            float2 v1 = make_float2(acc[mf][nf][2], acc[mf][nf][3]);
            if (SIG) {
                float b0 = bias[col], b1 = bias[col + 1];
                v0.x = 1.0f / (1.0f + expf(-(v0.x + b0)));
                v0.y = 1.0f / (1.0f + expf(-(v0.y + b1)));
                v1.x = 1.0f / (1.0f + expf(-(v1.x + b0)));
                v1.y = 1.0f / (1.0f + expf(-(v1.y + b1)));
            }
            if (col < nvalid) {
                *(float2*)(C + (size_t)r0 * ldc + col) = v0;
                *(float2*)(C + (size_t)(r0 + 8) * ldc + col) = v1;
            }
        }
    }
}

// ---------------- host launch ----------------
extern "C" void kernel_launch(void* const* d_in, const int* in_sizes, int n_in,
                              void* d_out, int out_size)
{
    const float* x    = (const float*)d_in[0];   // [8192, 2048]
    const float* W    = (const float*)d_in[1];   // [2048, 1023]
    const float* b    = (const float*)d_in[2];   // [1023]
    const float* leaf = (const float*)d_in[3];   // [1024, 1000]
    float*       out  = (float*)d_out;           // [8192, 1000]

    __half *xh, *WhT, *pph, *lpTh;
    float *bp, *dec;
    cudaGetSymbolAddress((void**)&xh,   g_xh);
    cudaGetSymbolAddress((void**)&WhT,  g_WhT);
    cudaGetSymbolAddress((void**)&bp,   g_bp);
    cudaGetSymbolAddress((void**)&dec,  g_dec);
    cudaGetSymbolAddress((void**)&pph,  g_pph);
    cudaGetSymbolAddress((void**)&lpTh, g_lpTh);

    static bool attr_set = false;
    if (!attr_set) {
        cudaFuncSetAttribute(gemm_h<true>,  cudaFuncAttributeMaxDynamicSharedMemorySize, SMEM_GEMM);
        cudaFuncSetAttribute(gemm_h<false>, cudaFuncAttributeMaxDynamicSharedMemorySize, SMEM_GEMM);
        attr_set = true;
    }

    // prep
    convert_x<<<(BN_ * DN_) / (256 * 8), 256>>>(x);
    transpose_W<<<dim3(DN_ / 32, NL_ / 32), dim3(32, 8)>>>(W);
    pad_b_kernel<<<4, 256>>>(b);
    softmax_kernel<<<NL_, 256>>>(leaf);
    transpose_lp<<<dim3(32, 32), dim3(32, 8)>>>();

    // 1) decisions = sigmoid(x @ W + b)   [8192,1024] fp32
    gemm_h<true><<<dim3(NL_ / BNT, BN_ / BM), 128, SMEM_GEMM>>>(
        xh, WhT, bp, dec, DN_, DN_, DN_, NL_, NL_);

    // 2) tree expansion -> pp fp16 [8192,1024]  (sync-free unwind)
    pp_kernel<<<BN_, 256>>>();

    // 3) out = pp @ leaf_probs   [8192,1000]
    gemm_h<false><<<dim3(NL_ / BNT, BN_ / BM), 128, SMEM_GEMM>>>(
        pph, lpTh, nullptr, out, NL_, NL_, NL_, CN_, CN_);
}

// round 9
// speedup vs baseline: 1.4466x; 1.0083x over previous
#include <cuda_runtime.h>
#include <cuda_fp16.h>
#include <stdint.h>
#include <math.h>

// ---------------- problem constants ----------------
#define BN_ 8192   // batch
#define DN_ 2048   // feature dim
#define NI_ 1023   // inner nodes
#define NL_ 1024   // leaves / padded inner count
#define CN_ 1000   // classes

// ---------------- device-global scratch ----------------
__device__ __half g_xh[(size_t)BN_ * DN_];        // x in fp16
__device__ __half g_WhT[NL_ * DN_];               // W^T padded fp16: [1024 n][2048 k]
__device__ float  g_bp[NL_];
__device__ float  g_dec[(size_t)BN_ * NL_];       // decisions [8192][1024] (fp32)
__device__ __half g_pph[(size_t)BN_ * NL_];       // path probs fp16 [8192][1024]
__device__ float  g_lp[NL_ * NL_];                // softmax(leaf) fp32 [1024][1024]
__device__ __half g_lpTh[NL_ * NL_];              // transposed fp16 [1024 cls][1024 leaf]

// ---------------- helpers ----------------
__device__ __forceinline__ uint32_t smem_u32(const void* p) {
    uint32_t a;
    asm("{ .reg .u64 t; cvta.to.shared.u64 t, %1; cvt.u32.u64 %0, t; }" : "=r"(a) : "l"(p));
    return a;
}
__device__ __forceinline__ void cpasync16(uint32_t dst, const void* src) {
    asm volatile("cp.async.cg.shared.global [%0], [%1], 16;" :: "r"(dst), "l"(src) : "memory");
}
__device__ __forceinline__ void ldsm4(uint32_t* r, uint32_t addr) {
    asm volatile("ldmatrix.sync.aligned.m8n8.x4.shared.b16 {%0,%1,%2,%3}, [%4];"
        : "=r"(r[0]), "=r"(r[1]), "=r"(r[2]), "=r"(r[3]) : "r"(addr));
}
__device__ __forceinline__ void mma16816(float* d, const uint32_t* a, uint32_t b0, uint32_t b1) {
    asm volatile("mma.sync.aligned.m16n8k16.row.col.f32.f16.f16.f32 "
        "{%0,%1,%2,%3}, {%4,%5,%6,%7}, {%8,%9}, {%0,%1,%2,%3};"
        : "+f"(d[0]), "+f"(d[1]), "+f"(d[2]), "+f"(d[3])
        : "r"(a[0]), "r"(a[1]), "r"(a[2]), "r"(a[3]), "r"(b0), "r"(b1));
}

// ================= fused prep: softmax | transpose_W | convert_x | pad_b =================
// block ranges (long-latency first):
//   [0, 1024)            softmax row
//   [1024, 3072)         transpose_W (2048 blocks: x = b%64 -> k0, y = b/64 -> n0)
//   [3072, 11264)        convert_x   (8192 blocks)
//   [11264, 11268)       pad_b       (4 blocks)
#define PREP_SM   0
#define PREP_TW   1024
#define PREP_CX   3072
#define PREP_PB   11264
#define PREP_GRID 11268

__global__ __launch_bounds__(256) void prep_fused(
    const float* __restrict__ x, const float* __restrict__ W,
    const float* __restrict__ b, const float* __restrict__ ld)
{
    __shared__ float smem_u[32 * 33];
    int bid = blockIdx.x;
    int tid = threadIdx.x;

    if (bid < PREP_TW) {
        // ---- softmax row of leaf_dist -> g_lp [1024,1024] fp32, pad zeroed ----
        int row = bid;
        const float* r = ld + (size_t)row * CN_;
        float*       o = g_lp + (size_t)row * NL_;
        float* sred = smem_u;   // 8 floats

        float mx = -3.4e38f;
        for (int i = tid; i < CN_; i += 256) mx = fmaxf(mx, r[i]);
        #pragma unroll
        for (int s = 16; s; s >>= 1) mx = fmaxf(mx, __shfl_xor_sync(0xffffffffu, mx, s));
        if ((tid & 31) == 0) sred[tid >> 5] = mx;
        __syncthreads();
        mx = sred[0];
        #pragma unroll
        for (int w = 1; w < 8; w++) mx = fmaxf(mx, sred[w]);
        __syncthreads();

        float sum = 0.0f;
        for (int i = tid; i < CN_; i += 256) sum += expf(r[i] - mx);
        #pragma unroll
        for (int s = 16; s; s >>= 1) sum += __shfl_xor_sync(0xffffffffu, sum, s);
        if ((tid & 31) == 0) sred[tid >> 5] = sum;
        __syncthreads();
        sum = 0.0f;
        #pragma unroll
        for (int w = 0; w < 8; w++) sum += sred[w];
        float inv = 1.0f / sum;

        for (int i = tid; i < CN_; i += 256) o[i] = expf(r[i] - mx) * inv;
        for (int i = CN_ + tid; i < NL_; i += 256) o[i] = 0.0f;
    } else if (bid < PREP_CX) {
        // ---- W [2048 k][1023 n] -> g_WhT [1024 n][2048 k] fp16, pad with 0 ----
        int b2 = bid - PREP_TW;
        int k0 = (b2 & 63) * 32;        // 64 k-blocks
        int n0 = (b2 >> 6) * 32;        // 32 n-blocks
        int tx = tid & 31, ty = tid >> 5;   // 32 x 8
        float* t = smem_u;              // [32][33]
        #pragma unroll
        for (int i = 0; i < 32; i += 8) {
            int n = n0 + tx;
            t[(ty + i) * 33 + tx] = (n < NI_) ? W[(size_t)(k0 + ty + i) * NI_ + n] : 0.0f;
        }
        __syncthreads();
        #pragma unroll
        for (int i = 0; i < 32; i += 8)
            g_WhT[(size_t)(n0 + ty + i) * DN_ + k0 + tx] = __float2half_rn(t[tx * 33 + ty + i]);
    } else if (bid < PREP_PB) {
        // ---- x fp32 -> fp16 ----
        int b2 = bid - PREP_CX;
        size_t i = ((size_t)b2 * 256 + tid) * 8;
        float4 v0 = *(const float4*)(x + i);
        float4 v1 = *(const float4*)(x + i + 4);
        __half2 h[4];
        h[0] = __floats2half2_rn(v0.x, v0.y);
        h[1] = __floats2half2_rn(v0.z, v0.w);
        h[2] = __floats2half2_rn(v1.x, v1.y);
        h[3] = __floats2half2_rn(v1.z, v1.w);
        *(uint4*)(g_xh + i) = *(uint4*)h;
    } else {
        // ---- pad b ----
        int i = (bid - PREP_PB) * 256 + tid;
        if (i < NL_) g_bp[i] = (i < NI_) ? b[i] : 0.0f;
    }
}

// ================= fused mid: pp unwind | transpose_lp =================
//   [0, 8192)        pp row (sync-free unwind, verified)
//   [8192, 9216)     transpose_lp (1024 blocks: x = b&31, y = b>>5)
#define MID_PP  0
#define MID_TL  8192
#define MID_GRID 9216

__global__ __launch_bounds__(256) void mid_fused() {
    __shared__ float smem_u[32 * 33 > NL_ ? 32 * 33 : NL_];
    int bid = blockIdx.x;
    int tid = threadIdx.x;

    if (bid < MID_TL) {
        // ---- pp unwind ----
        int row = bid;
        float* ds = smem_u;
        const float* dr = g_dec + (size_t)row * NL_;
        for (int i = tid; i < NL_; i += 256) ds[i] = dr[i];
        __syncthreads();

        __half* po = g_pph + (size_t)row * NL_;
        #pragma unroll
        for (int jj = 0; jj < 4; jj++) {
            int j = tid + jj * 256;
            float p = 1.0f;
            int idx = j;
            #pragma unroll
            for (int d = 9; d >= 0; d--) {
                int L = 1 << d;
                int i2 = (idx < L) ? (idx << 1) : (((idx - L) << 1) | 1);
                bool left = i2 < L;
                int node = (L - 1) + (left ? i2 : (i2 - L));
                float dd = ds[node];
                p *= left ? dd : (1.0f - dd);
                idx = i2 & (L - 1);
            }
            po[j] = __float2half_rn(p);
        }
    } else {
        // ---- g_lp [leaf][cls] fp32 -> g_lpTh [cls][leaf] fp16 ----
        int b2 = bid - MID_TL;
        int r0 = (b2 & 31) * 32, c0 = (b2 >> 5) * 32;
        int tx = tid & 31, ty = tid >> 5;
        float* t = smem_u;   // [32][33]
        #pragma unroll
        for (int i = 0; i < 32; i += 8)
            t[(ty + i) * 33 + tx] = g_lp[(size_t)(r0 + ty + i) * NL_ + c0 + tx];
        __syncthreads();
        #pragma unroll
        for (int i = 0; i < 32; i += 8)
            g_lpTh[(size_t)(c0 + ty + i) * NL_ + r0 + tx] = __float2half_rn(t[tx * 33 + ty + i]);
    }
}

// ---------------- fp16 mma.sync GEMM: 64x128x64 tiles, 4-stage cp.async, ldmatrix ----------------
// 1024 CTAs per GEMM -> per-SM tile count 6.92/7 => ~99% schedule efficiency
#define BM   64
#define BNT  128
#define BKH  64                                   // k-tile in halves
#define STG  4
#define PADH 72                                   // halves per smem row (144B)
#define SSTAGE_H ((BM + BNT) * PADH)              // halves per stage = 13824
#define SMEM_GEMM (STG * SSTAGE_H * 2)            // 110592 bytes

template <bool SIG>
__global__ __launch_bounds__(128, 2) void gemm_h(
    const __half* __restrict__ A, const __half* __restrict__ Bm,
    const float* __restrict__ bias, float* __restrict__ C,
    int K, int lda, int ldb, int ldc, int nvalid)
{
    extern __shared__ __half smh[];
    const int tid  = threadIdx.x;
    const int wid  = tid >> 5, lane = tid & 31;
    const int gid  = lane >> 2, tig = lane & 3;
    const int m0   = (wid & 1) * 32, n0 = (wid >> 1) * 64;   // warp tile 32x64
    const int rowBase = blockIdx.y * BM;
    const int colBase = blockIdx.x * BNT;
    const uint32_t sb = smem_u32(smh);

    const __half* Ag = A + (size_t)rowBase * lda;
    const __half* Bg = Bm + (size_t)colBase * ldb;

    // ldmatrix lane addressing (R5-verified mapping)
    const int lrow  = (lane & 7) + ((lane >> 3) & 1) * 8;
    const int khalf = (lane >> 4) * 8;
    uint32_t offA[2], offB[4];
    #pragma unroll
    for (int mf = 0; mf < 2; mf++)
        offA[mf] = (uint32_t)(((m0 + mf * 16 + lrow) * PADH + khalf) * 2);
    #pragma unroll
    for (int p = 0; p < 4; p++)
        offB[p] = (uint32_t)((BM * PADH + (n0 + p * 16 + lrow) * PADH + khalf) * 2);

    float acc[2][8][4];
    #pragma unroll
    for (int mf = 0; mf < 2; mf++)
        #pragma unroll
        for (int nf = 0; nf < 8; nf++)
            #pragma unroll
            for (int q = 0; q < 4; q++) acc[mf][nf][q] = 0.0f;

    const int nkt = K / BKH;

    // stage loader: A 64 rows + B 128 rows, 8x16B chunks per row
    auto load_stage = [&](int s, int kt) {
        uint32_t abase = sb + (uint32_t)(s * SSTAGE_H) * 2;
        uint32_t bbase = abase + BM * PADH * 2;
        const __half* Ak = Ag + kt * BKH;
        const __half* Bk = Bg + kt * BKH;
        #pragma unroll
        for (int i = 0; i < 4; i++) {              // 512 A-chunks
            int idx = tid + i * 128;
            int row = idx >> 3, ch = idx & 7;
            cpasync16(abase + (uint32_t)(row * PADH * 2 + ch * 16), Ak + (size_t)row * lda + ch * 8);
        }
        #pragma unroll
        for (int i = 0; i < 8; i++) {              // 1024 B-chunks
            int idx = tid + i * 128;
            int row = idx >> 3, ch = idx & 7;
            cpasync16(bbase + (uint32_t)(row * PADH * 2 + ch * 16), Bk + (size_t)row * ldb + ch * 8);
        }
    };

    load_stage(0, 0);
    asm volatile("cp.async.commit_group;" ::: "memory");
    load_stage(1, 1);
    asm volatile("cp.async.commit_group;" ::: "memory");
    load_stage(2, 2);
    asm volatile("cp.async.commit_group;" ::: "memory");

    int stage = 0;
    for (int kt = 0; kt < nkt; kt++) {
        asm volatile("cp.async.wait_group 2;" ::: "memory");
        __syncthreads();

        if (kt + 3 < nkt) {
            int s3 = stage + 3; if (s3 >= STG) s3 -= STG;
            load_stage(s3, kt + 3);
        }
        asm volatile("cp.async.commit_group;" ::: "memory");

        uint32_t sbase = sb + (uint32_t)(stage * SSTAGE_H) * 2;
        #pragma unroll
        for (int ks = 0; ks < 4; ks++) {
            const uint32_t kb = ks * 32;   // 16 halves per kstep
            uint32_t a[2][4], b[4][4];
            #pragma unroll
            for (int mf = 0; mf < 2; mf++) ldsm4(a[mf], sbase + offA[mf] + kb);
            #pragma unroll
            for (int p = 0; p < 4; p++)   ldsm4(b[p],  sbase + offB[p] + kb);
            // b[p]: r0=(nlo,klo) r1=(nhi,klo) r2=(nlo,khi) r3=(nhi,khi)
            #pragma unroll
            for (int mf = 0; mf < 2; mf++)
                #pragma unroll
                for (int p = 0; p < 4; p++) {
                    mma16816(acc[mf][2 * p],     a[mf], b[p][0], b[p][2]);
                    mma16816(acc[mf][2 * p + 1], a[mf], b[p][1], b[p][3]);
                }
        }
        stage++; if (stage == STG) stage = 0;
    }

    // epilogue
    #pragma unroll
    for (int mf = 0; mf < 2; mf++) {
        int r0 = rowBase + m0 + mf * 16 + gid;
        #pragma unroll
        for (int nf = 0; nf < 8; nf++) {
            int col = colBase + n0 + nf * 8 + tig * 2;
            float2 v0 = make_float2(acc[mf][nf][0], acc[mf][nf][1]);
            float2 v1 = make_float2(acc[mf][nf][2], acc[mf][nf][3]);
            if (SIG) {
                float b0 = bias[col], b1 = bias[col + 1];
                v0.x = 1.0f / (1.0f + expf(-(v0.x + b0)));
                v0.y = 1.0f / (1.0f + expf(-(v0.y + b1)));
                v1.x = 1.0f / (1.0f + expf(-(v1.x + b0)));
                v1.y = 1.0f / (1.0f + expf(-(v1.y + b1)));
            }
            if (col < nvalid) {
                *(float2*)(C + (size_t)r0 * ldc + col) = v0;
                *(float2*)(C + (size_t)(r0 + 8) * ldc + col) = v1;
            }
        }
    }
}

// ---------------- host launch ----------------
extern "C" void kernel_launch(void* const* d_in, const int* in_sizes, int n_in,
                              void* d_out, int out_size)
{
    const float* x    = (const float*)d_in[0];   // [8192, 2048]
    const float* W    = (const float*)d_in[1];   // [2048, 1023]
    const float* b    = (const float*)d_in[2];   // [1023]
    const float* leaf = (const float*)d_in[3];   // [1024, 1000]
    float*       out  = (float*)d_out;           // [8192, 1000]

    __half *xh, *WhT, *pph, *lpTh;
    float *bp, *dec;
    cudaGetSymbolAddress((void**)&xh,   g_xh);
    cudaGetSymbolAddress((void**)&WhT,  g_WhT);
    cudaGetSymbolAddress((void**)&bp,   g_bp);
    cudaGetSymbolAddress((void**)&dec,  g_dec);
    cudaGetSymbolAddress((void**)&pph,  g_pph);
    cudaGetSymbolAddress((void**)&lpTh, g_lpTh);

    static bool attr_set = false;
    if (!attr_set) {
        cudaFuncSetAttribute(gemm_h<true>,  cudaFuncAttributeMaxDynamicSharedMemorySize, SMEM_GEMM);
        cudaFuncSetAttribute(gemm_h<false>, cudaFuncAttributeMaxDynamicSharedMemorySize, SMEM_GEMM);
        attr_set = true;
    }

    // 1) fused prep: softmax | transpose_W | convert_x | pad_b
    prep_fused<<<PREP_GRID, 256>>>(x, W, b, leaf);

    // 2) decisions = sigmoid(x @ W + b)   [8192,1024] fp32   (1024 CTAs)
    gemm_h<true><<<dim3(NL_ / BNT, BN_ / BM), 128, SMEM_GEMM>>>(
        xh, WhT, bp, dec, DN_, DN_, DN_, NL_, NL_);

    // 3) fused mid: pp unwind | transpose_lp
    mid_fused<<<MID_GRID, 256>>>();

    // 4) out = pp @ leaf_probs   [8192,1000]   (1024 CTAs)
    gemm_h<false><<<dim3(NL_ / BNT, BN_ / BM), 128, SMEM_GEMM>>>(
        pph, lpTh, nullptr, out, NL_, NL_, NL_, CN_, CN_);
}

// round 10
// speedup vs baseline: 1.5888x; 1.0983x over previous
#include <cuda_runtime.h>
#include <cuda_fp16.h>
#include <stdint.h>
#include <math.h>

// ---------------- problem constants ----------------
#define BN_ 8192   // batch
#define DN_ 2048   // feature dim
#define NI_ 1023   // inner nodes
#define NL_ 1024   // leaves / padded inner count
#define CN_ 1000   // classes

// ---------------- device-global scratch ----------------
__device__ __half g_xh[(size_t)BN_ * DN_];        // x in fp16
__device__ __half g_WhT[NL_ * DN_];               // W^T padded fp16: [1024 n][2048 k]
__device__ float  g_bp[NL_];
__device__ float  g_dec[(size_t)BN_ * NL_];       // decisions [8192][1024] (fp32)
__device__ __half g_pph[(size_t)BN_ * NL_];       // path probs fp16 [8192][1024]
__device__ float  g_lp[NL_ * NL_];                // softmax(leaf) fp32 [1024][1024]
__device__ __half g_lpTh[NL_ * NL_];              // transposed fp16 [1024 cls][1024 leaf]

// ---------------- helpers ----------------
__device__ __forceinline__ uint32_t smem_u32(const void* p) {
    uint32_t a;
    asm("{ .reg .u64 t; cvta.to.shared.u64 t, %1; cvt.u32.u64 %0, t; }" : "=r"(a) : "l"(p));
    return a;
}
__device__ __forceinline__ void cpasync16(uint32_t dst, const void* src) {
    asm volatile("cp.async.cg.shared.global [%0], [%1], 16;" :: "r"(dst), "l"(src) : "memory");
}
__device__ __forceinline__ void ldsm4(uint32_t* r, uint32_t addr) {
    asm volatile("ldmatrix.sync.aligned.m8n8.x4.shared.b16 {%0,%1,%2,%3}, [%4];"
        : "=r"(r[0]), "=r"(r[1]), "=r"(r[2]), "=r"(r[3]) : "r"(addr));
}
__device__ __forceinline__ void mma16816(float* d, const uint32_t* a, uint32_t b0, uint32_t b1) {
    asm volatile("mma.sync.aligned.m16n8k16.row.col.f32.f16.f16.f32 "
        "{%0,%1,%2,%3}, {%4,%5,%6,%7}, {%8,%9}, {%0,%1,%2,%3};"
        : "+f"(d[0]), "+f"(d[1]), "+f"(d[2]), "+f"(d[3])
        : "r"(a[0]), "r"(a[1]), "r"(a[2]), "r"(a[3]), "r"(b0), "r"(b1));
}

// ================= fused prep: softmax | transpose_W | convert_x | pad_b =================
#define PREP_SM   0
#define PREP_TW   1024
#define PREP_CX   3072
#define PREP_PB   11264
#define PREP_GRID 11268

__global__ __launch_bounds__(256) void prep_fused(
    const float* __restrict__ x, const float* __restrict__ W,
    const float* __restrict__ b, const float* __restrict__ ld)
{
    __shared__ float smem_u[32 * 33];
    int bid = blockIdx.x;
    int tid = threadIdx.x;

    if (bid < PREP_TW) {
        // ---- softmax row of leaf_dist -> g_lp [1024,1024] fp32, pad zeroed ----
        int row = bid;
        const float* r = ld + (size_t)row * CN_;
        float*       o = g_lp + (size_t)row * NL_;
        float* sred = smem_u;

        float mx = -3.4e38f;
        for (int i = tid; i < CN_; i += 256) mx = fmaxf(mx, r[i]);
        #pragma unroll
        for (int s = 16; s; s >>= 1) mx = fmaxf(mx, __shfl_xor_sync(0xffffffffu, mx, s));
        if ((tid & 31) == 0) sred[tid >> 5] = mx;
        __syncthreads();
        mx = sred[0];
        #pragma unroll
        for (int w = 1; w < 8; w++) mx = fmaxf(mx, sred[w]);
        __syncthreads();

        float sum = 0.0f;
        for (int i = tid; i < CN_; i += 256) sum += expf(r[i] - mx);
        #pragma unroll
        for (int s = 16; s; s >>= 1) sum += __shfl_xor_sync(0xffffffffu, sum, s);
        if ((tid & 31) == 0) sred[tid >> 5] = sum;
        __syncthreads();
        sum = 0.0f;
        #pragma unroll
        for (int w = 0; w < 8; w++) sum += sred[w];
        float inv = 1.0f / sum;

        for (int i = tid; i < CN_; i += 256) o[i] = expf(r[i] - mx) * inv;
        for (int i = CN_ + tid; i < NL_; i += 256) o[i] = 0.0f;
    } else if (bid < PREP_CX) {
        // ---- W [2048 k][1023 n] -> g_WhT [1024 n][2048 k] fp16, pad with 0 ----
        int b2 = bid - PREP_TW;
        int k0 = (b2 & 63) * 32;
        int n0 = (b2 >> 6) * 32;
        int tx = tid & 31, ty = tid >> 5;
        float* t = smem_u;
        #pragma unroll
        for (int i = 0; i < 32; i += 8) {
            int n = n0 + tx;
            t[(ty + i) * 33 + tx] = (n < NI_) ? W[(size_t)(k0 + ty + i) * NI_ + n] : 0.0f;
        }
        __syncthreads();
        #pragma unroll
        for (int i = 0; i < 32; i += 8)
            g_WhT[(size_t)(n0 + ty + i) * DN_ + k0 + tx] = __float2half_rn(t[tx * 33 + ty + i]);
    } else if (bid < PREP_PB) {
        // ---- x fp32 -> fp16 ----
        int b2 = bid - PREP_CX;
        size_t i = ((size_t)b2 * 256 + tid) * 8;
        float4 v0 = *(const float4*)(x + i);
        float4 v1 = *(const float4*)(x + i + 4);
        __half2 h[4];
        h[0] = __floats2half2_rn(v0.x, v0.y);
        h[1] = __floats2half2_rn(v0.z, v0.w);
        h[2] = __floats2half2_rn(v1.x, v1.y);
        h[3] = __floats2half2_rn(v1.z, v1.w);
        *(uint4*)(g_xh + i) = *(uint4*)h;
    } else {
        int i = (bid - PREP_PB) * 256 + tid;
        if (i < NL_) g_bp[i] = (i < NI_) ? b[i] : 0.0f;
    }
}

// ================= fused mid: pp unwind | transpose_lp =================
#define MID_TL  8192
#define MID_GRID 9216

__global__ __launch_bounds__(256) void mid_fused() {
    __shared__ float smem_u[32 * 33 > NL_ ? 32 * 33 : NL_];
    int bid = blockIdx.x;
    int tid = threadIdx.x;

    if (bid < MID_TL) {
        // ---- pp unwind (verified) ----
        int row = bid;
        float* ds = smem_u;
        const float* dr = g_dec + (size_t)row * NL_;
        for (int i = tid; i < NL_; i += 256) ds[i] = dr[i];
        __syncthreads();

        __half* po = g_pph + (size_t)row * NL_;
        #pragma unroll
        for (int jj = 0; jj < 4; jj++) {
            int j = tid + jj * 256;
            float p = 1.0f;
            int idx = j;
            #pragma unroll
            for (int d = 9; d >= 0; d--) {
                int L = 1 << d;
                int i2 = (idx < L) ? (idx << 1) : (((idx - L) << 1) | 1);
                bool left = i2 < L;
                int node = (L - 1) + (left ? i2 : (i2 - L));
                float dd = ds[node];
                p *= left ? dd : (1.0f - dd);
                idx = i2 & (L - 1);
            }
            po[j] = __float2half_rn(p);
        }
    } else {
        // ---- g_lp [leaf][cls] fp32 -> g_lpTh [cls][leaf] fp16 ----
        int b2 = bid - MID_TL;
        int r0 = (b2 & 31) * 32, c0 = (b2 >> 5) * 32;
        int tx = tid & 31, ty = tid >> 5;
        float* t = smem_u;
        #pragma unroll
        for (int i = 0; i < 32; i += 8)
            t[(ty + i) * 33 + tx] = g_lp[(size_t)(r0 + ty + i) * NL_ + c0 + tx];
        __syncthreads();
        #pragma unroll
        for (int i = 0; i < 32; i += 8)
            g_lpTh[(size_t)(c0 + ty + i) * NL_ + r0 + tx] = __float2half_rn(t[tx * 33 + ty + i]);
    }
}

// ---------------- fp16 mma.sync GEMM: 128x128x64, 256 threads (8 warps x 32x64), 3-stage ----------------
#define BM   128
#define BNT  128
#define BKH  64                                   // k-tile in halves
#define STG  3
#define PADH 72                                   // halves per smem row (144B)
#define SSTAGE_H ((BM + BNT) * PADH)              // halves per stage = 18432
#define SMEM_GEMM (STG * SSTAGE_H * 2)            // 110592 bytes

template <bool SIG>
__global__ __launch_bounds__(256, 2) void gemm_h(
    const __half* __restrict__ A, const __half* __restrict__ Bm,
    const float* __restrict__ bias, float* __restrict__ C,
    int K, int lda, int ldb, int ldc, int nvalid)
{
    extern __shared__ __half smh[];
    const int tid  = threadIdx.x;
    const int wid  = tid >> 5, lane = tid & 31;
    const int gid  = lane >> 2, tig = lane & 3;
    const int m0   = (wid & 3) * 32, n0 = (wid >> 2) * 64;   // warp tile 32x64
    const int rowBase = blockIdx.y * BM;
    const int colBase = blockIdx.x * BNT;
    const uint32_t sb = smem_u32(smh);

    const __half* Ag = A + (size_t)rowBase * lda;
    const __half* Bg = Bm + (size_t)colBase * ldb;

    // ldmatrix lane addressing (R5-verified mapping)
    const int lrow  = (lane & 7) + ((lane >> 3) & 1) * 8;
    const int khalf = (lane >> 4) * 8;
    uint32_t offA[2], offB[4];
    #pragma unroll
    for (int mf = 0; mf < 2; mf++)
        offA[mf] = (uint32_t)(((m0 + mf * 16 + lrow) * PADH + khalf) * 2);
    #pragma unroll
    for (int p = 0; p < 4; p++)
        offB[p] = (uint32_t)((BM * PADH + (n0 + p * 16 + lrow) * PADH + khalf) * 2);

    float acc[2][8][4];
    #pragma unroll
    for (int mf = 0; mf < 2; mf++)
        #pragma unroll
        for (int nf = 0; nf < 8; nf++)
            #pragma unroll
            for (int q = 0; q < 4; q++) acc[mf][nf][q] = 0.0f;

    const int nkt = K / BKH;

    // stage loader: 256 rows x 128B = 2048 x 16B chunks, 8 per thread
    auto load_stage = [&](int s, int kt) {
        uint32_t abase = sb + (uint32_t)(s * SSTAGE_H) * 2;
        uint32_t bbase = abase + BM * PADH * 2;
        const __half* Ak = Ag + kt * BKH;
        const __half* Bk = Bg + kt * BKH;
        #pragma unroll
        for (int i = 0; i < 4; i++) {              // 1024 A-chunks
            int idx = tid + i * 256;
            int row = idx >> 3, ch = idx & 7;
            cpasync16(abase + (uint32_t)(row * PADH * 2 + ch * 16), Ak + (size_t)row * lda + ch * 8);
        }
        #pragma unroll
        for (int i = 0; i < 4; i++) {              // 1024 B-chunks
            int idx = tid + i * 256;
            int row = idx >> 3, ch = idx & 7;
            cpasync16(bbase + (uint32_t)(row * PADH * 2 + ch * 16), Bk + (size_t)row * ldb + ch * 8);
        }
    };

    load_stage(0, 0);
    asm volatile("cp.async.commit_group;" ::: "memory");
    load_stage(1, 1);
    asm volatile("cp.async.commit_group;" ::: "memory");

    int stage = 0;
    for (int kt = 0; kt < nkt; kt++) {
        asm volatile("cp.async.wait_group 1;" ::: "memory");
        __syncthreads();

        if (kt + 2 < nkt) {
            int s2 = stage + 2; if (s2 >= STG) s2 -= STG;
            load_stage(s2, kt + 2);
        }
        asm volatile("cp.async.commit_group;" ::: "memory");

        uint32_t sbase = sb + (uint32_t)(stage * SSTAGE_H) * 2;
        #pragma unroll
        for (int ks = 0; ks < 4; ks++) {
            const uint32_t kb = ks * 32;   // 16 halves per kstep
            uint32_t a[2][4], b[4][4];
            #pragma unroll
            for (int mf = 0; mf < 2; mf++) ldsm4(a[mf], sbase + offA[mf] + kb);
            #pragma unroll
            for (int p = 0; p < 4; p++)   ldsm4(b[p],  sbase + offB[p] + kb);
            // b[p]: r0=(nlo,klo) r1=(nhi,klo) r2=(nlo,khi) r3=(nhi,khi)
            #pragma unroll
            for (int mf = 0; mf < 2; mf++)
                #pragma unroll
                for (int p = 0; p < 4; p++) {
                    mma16816(acc[mf][2 * p],     a[mf], b[p][0], b[p][2]);
                    mma16816(acc[mf][2 * p + 1], a[mf], b[p][1], b[p][3]);
                }
        }
        stage++; if (stage == STG) stage = 0;
    }

    // epilogue
    #pragma unroll
    for (int mf = 0; mf < 2; mf++) {
        int r0 = rowBase + m0 + mf * 16 + gid;
        #pragma unroll
        for (int nf = 0; nf < 8; nf++) {
            int col = colBase + n0 + nf * 8 + tig * 2;
            float2 v0 = make_float2(acc[mf][nf][0], acc[mf][nf][1]);
            float2 v1 = make_float2(acc[mf][nf][2], acc[mf][nf][3]);
            if (SIG) {
                float b0 = bias[col], b1 = bias[col + 1];
                v0.x = 1.0f / (1.0f + expf(-(v0.x + b0)));
                v0.y = 1.0f / (1.0f + expf(-(v0.y + b1)));
                v1.x = 1.0f / (1.0f + expf(-(v1.x + b0)));
                v1.y = 1.0f / (1.0f + expf(-(v1.y + b1)));
            }
            if (col < nvalid) {
                *(float2*)(C + (size_t)r0 * ldc + col) = v0;
                *(float2*)(C + (size_t)(r0 + 8) * ldc + col) = v1;
            }
        }
    }
}

// ---------------- host launch ----------------
extern "C" void kernel_launch(void* const* d_in, const int* in_sizes, int n_in,
                              void* d_out, int out_size)
{
    const float* x    = (const float*)d_in[0];   // [8192, 2048]
    const float* W    = (const float*)d_in[1];   // [2048, 1023]
    const float* b    = (const float*)d_in[2];   // [1023]
    const float* leaf = (const float*)d_in[3];   // [1024, 1000]
    float*       out  = (float*)d_out;           // [8192, 1000]

    __half *xh, *WhT, *pph, *lpTh;
    float *bp, *dec;
    cudaGetSymbolAddress((void**)&xh,   g_xh);
    cudaGetSymbolAddress((void**)&WhT,  g_WhT);
    cudaGetSymbolAddress((void**)&bp,   g_bp);
    cudaGetSymbolAddress((void**)&dec,  g_dec);
    cudaGetSymbolAddress((void**)&pph,  g_pph);
    cudaGetSymbolAddress((void**)&lpTh, g_lpTh);

    static bool attr_set = false;
    if (!attr_set) {
        cudaFuncSetAttribute(gemm_h<true>,  cudaFuncAttributeMaxDynamicSharedMemorySize, SMEM_GEMM);
        cudaFuncSetAttribute(gemm_h<false>, cudaFuncAttributeMaxDynamicSharedMemorySize, SMEM_GEMM);
        attr_set = true;
    }

    // 1) fused prep: softmax | transpose_W | convert_x | pad_b
    prep_fused<<<PREP_GRID, 256>>>(x, W, b, leaf);

    // 2) decisions = sigmoid(x @ W + b)   [8192,1024] fp32
    gemm_h<true><<<dim3(NL_ / BNT, BN_ / BM), 256, SMEM_GEMM>>>(
        xh, WhT, bp, dec, DN_, DN_, DN_, NL_, NL_);

    // 3) fused mid: pp unwind | transpose_lp
    mid_fused<<<MID_GRID, 256>>>();

    // 4) out = pp @ leaf_probs   [8192,1000]
    gemm_h<false><<<dim3(NL_ / BNT, BN_ / BM), 256, SMEM_GEMM>>>(
        pph, lpTh, nullptr, out, NL_, NL_, NL_, CN_, CN_);
}